// round 2
// baseline (speedup 1.0000x reference)
#include <cuda_runtime.h>

#define NB  4
#define NS  2048
#define ND  512
#define NH  8
#define NHD 64
#define NROWS (NB*NS)   // 8192

// Scratch (device globals — no allocation inside kernel_launch)
__device__ float g_Q[NB*NH*NS*NHD];   // [B,H,S,64]
__device__ float g_K[NB*NH*NS*NHD];
__device__ float g_V[NB*NH*NS*NHD];
__device__ float g_O[NB*NS*ND];       // [B,S,D] merged attention output

// ---------------------------------------------------------------------------
// Fused QKV projection: C = A[8192,512] @ W[512,512], output head-split.
// grid = (8, 128, 3), block = 256. 64x64 C tile, 16-deep k tiles, 4x4 microtile.
// ---------------------------------------------------------------------------
__global__ __launch_bounds__(256) void proj_kernel(
    const float* __restrict__ X, const float* __restrict__ Y, const float* __restrict__ Z,
    const float* __restrict__ Wq, const float* __restrict__ Wk, const float* __restrict__ Wo)
{
    __shared__ float As[16][64];   // [k][row]  (k-major so reads are float4 on rows)
    __shared__ float Bs[16][64];   // [k][col]

    const float* A; const float* W; float* Out;
    if (blockIdx.z == 0)      { A = X; W = Wq; Out = g_Q; }
    else if (blockIdx.z == 1) { A = Y; W = Wk; Out = g_K; }
    else                      { A = Z; W = Wo; Out = g_V; }   // NOTE: V uses Wo (faithful to ref)

    const int t  = threadIdx.x;
    const int tx = t & 15;          // col group 0..15
    const int ty = t >> 4;          // row group 0..15
    const int row0 = blockIdx.y * 64;
    const int col0 = blockIdx.x * 64;

    const int lar = t & 63;         // A-tile row this thread loads
    const int lac = (t >> 6) * 4;   // A-tile col group (0,4,8,12)
    const int lbr = t >> 4;         // W-tile row 0..15
    const int lbc = (t & 15) * 4;   // W-tile col group

    float acc[4][4] = {};

    for (int k0 = 0; k0 < ND; k0 += 16) {
        float4 av = *(const float4*)&A[(row0 + lar) * ND + k0 + lac];
        As[lac + 0][lar] = av.x;
        As[lac + 1][lar] = av.y;
        As[lac + 2][lar] = av.z;
        As[lac + 3][lar] = av.w;
        *(float4*)&Bs[lbr][lbc] = *(const float4*)&W[(k0 + lbr) * ND + col0 + lbc];
        __syncthreads();

        #pragma unroll
        for (int kk = 0; kk < 16; kk++) {
            float4 a = *(const float4*)&As[kk][ty * 4];
            float4 b = *(const float4*)&Bs[kk][tx * 4];
            acc[0][0] += a.x*b.x; acc[0][1] += a.x*b.y; acc[0][2] += a.x*b.z; acc[0][3] += a.x*b.w;
            acc[1][0] += a.y*b.x; acc[1][1] += a.y*b.y; acc[1][2] += a.y*b.z; acc[1][3] += a.y*b.w;
            acc[2][0] += a.z*b.x; acc[2][1] += a.z*b.y; acc[2][2] += a.z*b.z; acc[2][3] += a.z*b.w;
            acc[3][0] += a.w*b.x; acc[3][1] += a.w*b.y; acc[3][2] += a.w*b.z; acc[3][3] += a.w*b.w;
        }
        __syncthreads();
    }

    // One 64-wide column tile == exactly one head (512/64 == 8 == NH).
    const int h = blockIdx.x;
    #pragma unroll
    for (int i = 0; i < 4; i++) {
        int r = row0 + ty * 4 + i;
        int b = r >> 11;        // r / 2048
        int s = r & 2047;
        float4 v = make_float4(acc[i][0], acc[i][1], acc[i][2], acc[i][3]);
        *(float4*)&Out[(((size_t)(b * NH + h) * NS) + s) * NHD + tx * 4] = v;
    }
}

// ---------------------------------------------------------------------------
// Flash-style attention for one (b,h) and one 64-row q tile.
// grid = (32, 32), block = 256. ReLU(score/8) -> online softmax -> P@V.
// Static smem exactly 48KB: Qt(16K) + KtPs(16K, K tile aliased with P tile) + Vs(16K).
// ---------------------------------------------------------------------------
__global__ __launch_bounds__(256) void attn_kernel()
{
    __shared__ float Qt[64][64];    // [d][qrow]   (d-major -> float4 reads on rows)
    __shared__ float KtPs[64][64];  // phase 1: K [d][kcol]; phase 2: P [qrow][kcol]
    __shared__ float Vs[64][64];    // [kcol][d]

    const int t  = threadIdx.x;
    const int tx = t & 15;
    const int ty = t >> 4;
    const int bh = blockIdx.y;
    const int q0 = blockIdx.x * 64;

    const float* Qg = g_Q + (size_t)bh * NS * NHD;
    const float* Kg = g_K + (size_t)bh * NS * NHD;
    const float* Vg = g_V + (size_t)bh * NS * NHD;

    const int lr = t & 63;          // tile row this thread loads
    const int lc = (t >> 6) * 16;   // 16-col span

    // Load Q tile transposed (d-major). Bank-conflict-free: lanes hit distinct banks (lr).
    #pragma unroll
    for (int c4 = 0; c4 < 4; c4++) {
        int col = lc + c4 * 4;
        float4 v = *(const float4*)&Qg[(q0 + lr) * NHD + col];
        Qt[col + 0][lr] = v.x;
        Qt[col + 1][lr] = v.y;
        Qt[col + 2][lr] = v.z;
        Qt[col + 3][lr] = v.w;
    }

    float m[4], l[4], o[4][4];
    #pragma unroll
    for (int i = 0; i < 4; i++) {
        m[i] = 0.f; l[i] = 0.f;               // scores >= 0 post-ReLU, so m=0 init is exact
        #pragma unroll
        for (int j = 0; j < 4; j++) o[i][j] = 0.f;
    }

    for (int j0 = 0; j0 < NS; j0 += 64) {
        __syncthreads();   // previous tile's P@V (reads Vs/KtPs) must be done

        // Load K (transposed, d-major) and V (row-major) tiles
        #pragma unroll
        for (int c4 = 0; c4 < 4; c4++) {
            int col = lc + c4 * 4;
            float4 kv = *(const float4*)&Kg[(j0 + lr) * NHD + col];
            KtPs[col + 0][lr] = kv.x;
            KtPs[col + 1][lr] = kv.y;
            KtPs[col + 2][lr] = kv.z;
            KtPs[col + 3][lr] = kv.w;
            *(float4*)&Vs[lr][col] = *(const float4*)&Vg[(j0 + lr) * NHD + col];
        }
        __syncthreads();

        // S = Q @ K^T  (64x64x64)
        float s[4][4] = {};
        #pragma unroll
        for (int kk = 0; kk < 64; kk++) {
            float4 a = *(const float4*)&Qt[kk][ty * 4];
            float4 b = *(const float4*)&KtPs[kk][tx * 4];
            s[0][0] += a.x*b.x; s[0][1] += a.x*b.y; s[0][2] += a.x*b.z; s[0][3] += a.x*b.w;
            s[1][0] += a.y*b.x; s[1][1] += a.y*b.y; s[1][2] += a.y*b.z; s[1][3] += a.y*b.w;
            s[2][0] += a.z*b.x; s[2][1] += a.z*b.y; s[2][2] += a.z*b.z; s[2][3] += a.z*b.w;
            s[3][0] += a.w*b.x; s[3][1] += a.w*b.y; s[3][2] += a.w*b.z; s[3][3] += a.w*b.w;
        }

        // scale (1/sqrt(64) = 0.125 exact) + ReLU + online softmax update
        #pragma unroll
        for (int i = 0; i < 4; i++) {
            #pragma unroll
            for (int j = 0; j < 4; j++)
                s[i][j] = fmaxf(s[i][j] * 0.125f, 0.f);

            float mx = fmaxf(fmaxf(s[i][0], s[i][1]), fmaxf(s[i][2], s[i][3]));
            mx = fmaxf(mx, __shfl_xor_sync(0xffffffffu, mx, 1));
            mx = fmaxf(mx, __shfl_xor_sync(0xffffffffu, mx, 2));
            mx = fmaxf(mx, __shfl_xor_sync(0xffffffffu, mx, 4));
            mx = fmaxf(mx, __shfl_xor_sync(0xffffffffu, mx, 8));

            float mn    = fmaxf(m[i], mx);
            float alpha = __expf(m[i] - mn);
            float rsum  = 0.f;
            #pragma unroll
            for (int j = 0; j < 4; j++) {
                float p = __expf(s[i][j] - mn);
                s[i][j] = p;
                rsum += p;
            }
            rsum += __shfl_xor_sync(0xffffffffu, rsum, 1);
            rsum += __shfl_xor_sync(0xffffffffu, rsum, 2);
            rsum += __shfl_xor_sync(0xffffffffu, rsum, 4);
            rsum += __shfl_xor_sync(0xffffffffu, rsum, 8);

            l[i] = l[i] * alpha + rsum;
            m[i] = mn;
            #pragma unroll
            for (int j = 0; j < 4; j++) o[i][j] *= alpha;
        }

        __syncthreads();   // everyone done reading K tile before P overwrites it

        // Stage P into smem (aliases K tile)
        #pragma unroll
        for (int i = 0; i < 4; i++)
            *(float4*)&KtPs[ty * 4 + i][tx * 4] =
                make_float4(s[i][0], s[i][1], s[i][2], s[i][3]);
        __syncthreads();

        // O += P @ V  (64x64x64)
        #pragma unroll
        for (int j = 0; j < 64; j++) {
            float4 bv = *(const float4*)&Vs[j][tx * 4];
            float a0 = KtPs[ty * 4 + 0][j];
            float a1 = KtPs[ty * 4 + 1][j];
            float a2 = KtPs[ty * 4 + 2][j];
            float a3 = KtPs[ty * 4 + 3][j];
            o[0][0] += a0*bv.x; o[0][1] += a0*bv.y; o[0][2] += a0*bv.z; o[0][3] += a0*bv.w;
            o[1][0] += a1*bv.x; o[1][1] += a1*bv.y; o[1][2] += a1*bv.z; o[1][3] += a1*bv.w;
            o[2][0] += a2*bv.x; o[2][1] += a2*bv.y; o[2][2] += a2*bv.z; o[2][3] += a2*bv.w;
            o[3][0] += a3*bv.x; o[3][1] += a3*bv.y; o[3][2] += a3*bv.z; o[3][3] += a3*bv.w;
        }
    }

    // Normalize and write merged [B,S,D]
    const int b = bh >> 3;
    const int h = bh & 7;
    #pragma unroll
    for (int i = 0; i < 4; i++) {
        float inv = 1.f / l[i];
        int srow = q0 + ty * 4 + i;
        float4 v = make_float4(o[i][0]*inv, o[i][1]*inv, o[i][2]*inv, o[i][3]*inv);
        *(float4*)&g_O[((size_t)(b * NS + srow)) * ND + h * NHD + tx * 4] = v;
    }
}

// ---------------------------------------------------------------------------
// Output projection: out = g_O[8192,512] @ Wo[512,512], plain row-major out.
// grid = (8, 128), block = 256.
// ---------------------------------------------------------------------------
__global__ __launch_bounds__(256) void oproj_kernel(
    const float* __restrict__ Wo, float* __restrict__ out)
{
    __shared__ float As[16][64];
    __shared__ float Bs[16][64];

    const int t  = threadIdx.x;
    const int tx = t & 15;
    const int ty = t >> 4;
    const int row0 = blockIdx.y * 64;
    const int col0 = blockIdx.x * 64;

    const int lar = t & 63;
    const int lac = (t >> 6) * 4;
    const int lbr = t >> 4;
    const int lbc = (t & 15) * 4;

    float acc[4][4] = {};

    for (int k0 = 0; k0 < ND; k0 += 16) {
        float4 av = *(const float4*)&g_O[(size_t)(row0 + lar) * ND + k0 + lac];
        As[lac + 0][lar] = av.x;
        As[lac + 1][lar] = av.y;
        As[lac + 2][lar] = av.z;
        As[lac + 3][lar] = av.w;
        *(float4*)&Bs[lbr][lbc] = *(const float4*)&Wo[(k0 + lbr) * ND + col0 + lbc];
        __syncthreads();

        #pragma unroll
        for (int kk = 0; kk < 16; kk++) {
            float4 a = *(const float4*)&As[kk][ty * 4];
            float4 b = *(const float4*)&Bs[kk][tx * 4];
            acc[0][0] += a.x*b.x; acc[0][1] += a.x*b.y; acc[0][2] += a.x*b.z; acc[0][3] += a.x*b.w;
            acc[1][0] += a.y*b.x; acc[1][1] += a.y*b.y; acc[1][2] += a.y*b.z; acc[1][3] += a.y*b.w;
            acc[2][0] += a.z*b.x; acc[2][1] += a.z*b.y; acc[2][2] += a.z*b.z; acc[2][3] += a.z*b.w;
            acc[3][0] += a.w*b.x; acc[3][1] += a.w*b.y; acc[3][2] += a.w*b.z; acc[3][3] += a.w*b.w;
        }
        __syncthreads();
    }

    #pragma unroll
    for (int i = 0; i < 4; i++) {
        int r = row0 + ty * 4 + i;
        float4 v = make_float4(acc[i][0], acc[i][1], acc[i][2], acc[i][3]);
        *(float4*)&out[(size_t)r * ND + col0 + tx * 4] = v;
    }
}

// ---------------------------------------------------------------------------
extern "C" void kernel_launch(void* const* d_in, const int* in_sizes, int n_in,
                              void* d_out, int out_size)
{
    const float* X  = (const float*)d_in[0];
    const float* Y  = (const float*)d_in[1];
    const float* Z  = (const float*)d_in[2];
    const float* Wq = (const float*)d_in[3];
    const float* Wk = (const float*)d_in[4];
    /* d_in[5] = Wv — intentionally unused (reference uses Wo for V) */
    const float* Wo = (const float*)d_in[6];
    float* out = (float*)d_out;

    proj_kernel<<<dim3(8, 128, 3), 256>>>(X, Y, Z, Wq, Wk, Wo);
    attn_kernel<<<dim3(32, 32), 256>>>();
    oproj_kernel<<<dim3(8, 128), 256>>>(Wo, out);
}